// round 3
// baseline (speedup 1.0000x reference)
#include <cuda_runtime.h>
#include <cuda_bf16.h>

// Problem constants (shapes are static for this problem instance).
constexpr int CDIM = 768;
constexpr int NHD  = 12;
constexpr int HD   = 64;
constexpr int WSZ  = 14;
constexpr int NT   = WSZ * WSZ;        // 196 tokens per window
constexpr int NWIN = 256;              // 16 images * 4*4 windows (56/14 = 4, no padding)
constexpr int M1   = NWIN * NT;        // 50176 rows
constexpr int QKVN = 3 * CDIM;         // 2304

// Scratch (device globals; runtime allocation is forbidden).
__device__ float g_q[(long)NWIN * NHD * NT * HD];
__device__ float g_k[(long)NWIN * NHD * NT * HD];
__device__ float g_v[(long)NWIN * NHD * NT * HD];
__device__ float g_att[(long)M1 * CDIM];

// ---------------------------------------------------------------------------
// Kernel 1: fused window-partition + QKV GEMM (+bias, q*scale)
// A = x gathered through the window permutation  [M1, 768]  (K contiguous)
// B = qkv_w [2304, 768] row-major               (K contiguous)  -> TN GEMM
// Tiles: 128x128x16, 256 threads, 8x8 microtile.
// ---------------------------------------------------------------------------
__global__ __launch_bounds__(256, 2) void k_qkv(
    const float* __restrict__ x, const float* __restrict__ w,
    const float* __restrict__ qb, const float* __restrict__ vb)
{
    __shared__ float As[16][128];   // As[k][m]
    __shared__ float Bs[16][128];   // Bs[k][n]

    const int tid = threadIdx.x;
    const int bm = blockIdx.y, bn = blockIdx.x;
    const int m0 = bm * 128, n0 = bn * 128;

    // Per-thread load coordinates: each thread loads 2 consecutive float4
    // (32 bytes) of one row of A and one row of B per K-step.
    const int lrow = tid >> 1;
    const int lcol = (tid & 1) * 8;

    // Map A-tile row -> global token through the window permutation (once).
    {
        // nothing: computed below into aptr
    }
    const int am   = m0 + lrow;
    const int wwin = am / NT;
    const int nn   = am - wwin * NT;
    const int bimg = wwin >> 4;
    const int wi   = wwin & 15;
    const int rr   = (wi >> 2) * WSZ + nn / WSZ;
    const int cc   = (wi & 3) * WSZ + nn % WSZ;
    const float* aptr = x + ((long)bimg * 3136 + (long)rr * 56 + cc) * CDIM + lcol;
    const float* bptr = w + (long)(n0 + lrow) * CDIM + lcol;

    const int tr = tid >> 4;       // 0..15
    const int tc = tid & 15;       // 0..15

    float acc[8][8];
#pragma unroll
    for (int i = 0; i < 8; i++)
#pragma unroll
        for (int j = 0; j < 8; j++) acc[i][j] = 0.f;

    for (int k0 = 0; k0 < CDIM; k0 += 16) {
        float4 a0 = *(const float4*)(aptr + k0);
        float4 a1 = *(const float4*)(aptr + k0 + 4);
        float4 b0 = *(const float4*)(bptr + k0);
        float4 b1 = *(const float4*)(bptr + k0 + 4);
        As[lcol + 0][lrow] = a0.x; As[lcol + 1][lrow] = a0.y;
        As[lcol + 2][lrow] = a0.z; As[lcol + 3][lrow] = a0.w;
        As[lcol + 4][lrow] = a1.x; As[lcol + 5][lrow] = a1.y;
        As[lcol + 6][lrow] = a1.z; As[lcol + 7][lrow] = a1.w;
        Bs[lcol + 0][lrow] = b0.x; Bs[lcol + 1][lrow] = b0.y;
        Bs[lcol + 2][lrow] = b0.z; Bs[lcol + 3][lrow] = b0.w;
        Bs[lcol + 4][lrow] = b1.x; Bs[lcol + 5][lrow] = b1.y;
        Bs[lcol + 6][lrow] = b1.z; Bs[lcol + 7][lrow] = b1.w;
        __syncthreads();

#pragma unroll
        for (int kk = 0; kk < 16; kk++) {
            float4 aA = *(const float4*)&As[kk][tr * 4];
            float4 aB = *(const float4*)&As[kk][64 + tr * 4];
            float4 bA = *(const float4*)&Bs[kk][tc * 4];
            float4 bB = *(const float4*)&Bs[kk][64 + tc * 4];
            float av[8] = {aA.x, aA.y, aA.z, aA.w, aB.x, aB.y, aB.z, aB.w};
            float bv[8] = {bA.x, bA.y, bA.z, bA.w, bB.x, bB.y, bB.z, bB.w};
#pragma unroll
            for (int i = 0; i < 8; i++)
#pragma unroll
                for (int j = 0; j < 8; j++) acc[i][j] += av[i] * bv[j];
        }
        __syncthreads();
    }

    // Epilogue: scatter into q/k/v with [win, head, tok, hd] layout.
#pragma unroll
    for (int i = 0; i < 8; i++) {
        const int m = m0 + ((i < 4) ? (tr * 4 + i) : (64 + tr * 4 + i - 4));
        const int w2 = m / NT;
        const int n2 = m - w2 * NT;
        const long base = (long)w2 * NHD * NT * HD;
#pragma unroll
        for (int j = 0; j < 8; j++) {
            const int jj = n0 + ((j < 4) ? (tc * 4 + j) : (64 + tc * 4 + j - 4));
            const int part = jj / CDIM;
            const int jr = jj - part * CDIM;
            const int hh = jr >> 6;
            const int dd = jr & 63;
            const long o = base + ((long)hh * NT + n2) * HD + dd;
            const float v = acc[i][j];
            if (part == 0)      g_q[o] = (v + qb[jr]) * 0.125f;   // scale = 64^-0.5
            else if (part == 1) g_k[o] = v;                        // k bias is zero
            else                g_v[o] = (v + vb[jr]);
        }
    }
}

// ---------------------------------------------------------------------------
// Kernel 2: windowed attention, one CTA per (window, head).
// Flash-style online softmax; K/V tiles of 14 rows in smem (broadcast reads);
// relative-position bias gathered from smem-resident per-head table.
// Writes output directly in global token order (window-reverse fused).
// ---------------------------------------------------------------------------
__global__ __launch_bounds__(224) void k_attn(const float* __restrict__ table)
{
    const int w  = blockIdx.x;   // 0..255
    const int h  = blockIdx.y;   // 0..11
    const int tid = threadIdx.x; // 0..223 ; rows 0..195 active

    __shared__ float Ks[14][64];
    __shared__ float Vs[14][64];
    __shared__ float tb[729];

    for (int t = tid; t < 729; t += 224) tb[t] = table[t * NHD + h];

    const long base = ((long)w * NHD + h) * NT * HD;
    const int i  = tid;
    const int iy = i / WSZ;
    const int ix = i - iy * WSZ;

    float4 q4[16];
    float4 o4[16];
    float mmax = -1e30f, lsum = 0.f;
    if (i < NT) {
        const float4* qp = (const float4*)(g_q + base + (long)i * HD);
#pragma unroll
        for (int kk = 0; kk < 16; kk++) {
            q4[kk] = qp[kk];
            o4[kk] = make_float4(0.f, 0.f, 0.f, 0.f);
        }
    }
    __syncthreads();   // table ready

    for (int jt = 0; jt < 14; jt++) {
        // Cooperative tile load: exactly one float4 per thread per tensor.
        const float4* kp = (const float4*)(g_k + base + (long)jt * 14 * HD);
        const float4* vp = (const float4*)(g_v + base + (long)jt * 14 * HD);
        ((float4*)Ks)[tid] = kp[tid];
        ((float4*)Vs)[tid] = vp[tid];
        __syncthreads();

        if (i < NT) {
            float s[14];
            float tmax = -1e30f;
#pragma unroll
            for (int jj = 0; jj < 14; jj++) {
                const float4* kr = (const float4*)Ks[jj];
                float a0 = 0.f, a1 = 0.f, a2 = 0.f, a3 = 0.f;
#pragma unroll
                for (int kk = 0; kk < 16; kk++) {
                    float4 kv = kr[kk];
                    float4 qv = q4[kk];
                    a0 += qv.x * kv.x; a1 += qv.y * kv.y;
                    a2 += qv.z * kv.z; a3 += qv.w * kv.w;
                }
                float sc = (a0 + a1) + (a2 + a3);
                sc += tb[(iy - jt + 13) * 27 + (ix - jj + 13)];
                s[jj] = sc;
                tmax = fmaxf(tmax, sc);
            }
            const float mnew = fmaxf(mmax, tmax);
            const float corr = __expf(mmax - mnew);
            mmax = mnew;
            lsum *= corr;
#pragma unroll
            for (int kk = 0; kk < 16; kk++) {
                o4[kk].x *= corr; o4[kk].y *= corr;
                o4[kk].z *= corr; o4[kk].w *= corr;
            }
#pragma unroll
            for (int jj = 0; jj < 14; jj++) {
                const float p = __expf(s[jj] - mmax);
                lsum += p;
                const float4* vr = (const float4*)Vs[jj];
#pragma unroll
                for (int kk = 0; kk < 16; kk++) {
                    float4 vv = vr[kk];
                    o4[kk].x += p * vv.x; o4[kk].y += p * vv.y;
                    o4[kk].z += p * vv.z; o4[kk].w += p * vv.w;
                }
            }
        }
        __syncthreads();
    }

    if (i < NT) {
        const float inv = 1.f / lsum;
        const int bimg = w >> 4, wi = w & 15;
        const int r = (wi >> 2) * WSZ + iy;
        const int c = (wi & 3) * WSZ + ix;
        float4* op = (float4*)(g_att + ((long)bimg * 3136 + (long)r * 56 + c) * CDIM + h * HD);
#pragma unroll
        for (int kk = 0; kk < 16; kk++) {
            float4 t = o4[kk];
            op[kk] = make_float4(t.x * inv, t.y * inv, t.z * inv, t.w * inv);
        }
    }
}

// ---------------------------------------------------------------------------
// Kernel 3: output projection GEMM (token-order rows; same tiling as k_qkv).
// ---------------------------------------------------------------------------
__global__ __launch_bounds__(256, 2) void k_proj(
    const float* __restrict__ pw, const float* __restrict__ pb,
    float* __restrict__ out)
{
    __shared__ float As[16][128];
    __shared__ float Bs[16][128];

    const int tid = threadIdx.x;
    const int bm = blockIdx.y, bn = blockIdx.x;
    const int m0 = bm * 128, n0 = bn * 128;

    const int lrow = tid >> 1;
    const int lcol = (tid & 1) * 8;
    const float* aptr = g_att + (long)(m0 + lrow) * CDIM + lcol;
    const float* bptr = pw + (long)(n0 + lrow) * CDIM + lcol;

    const int tr = tid >> 4;
    const int tc = tid & 15;

    float acc[8][8];
#pragma unroll
    for (int i = 0; i < 8; i++)
#pragma unroll
        for (int j = 0; j < 8; j++) acc[i][j] = 0.f;

    for (int k0 = 0; k0 < CDIM; k0 += 16) {
        float4 a0 = *(const float4*)(aptr + k0);
        float4 a1 = *(const float4*)(aptr + k0 + 4);
        float4 b0 = *(const float4*)(bptr + k0);
        float4 b1 = *(const float4*)(bptr + k0 + 4);
        As[lcol + 0][lrow] = a0.x; As[lcol + 1][lrow] = a0.y;
        As[lcol + 2][lrow] = a0.z; As[lcol + 3][lrow] = a0.w;
        As[lcol + 4][lrow] = a1.x; As[lcol + 5][lrow] = a1.y;
        As[lcol + 6][lrow] = a1.z; As[lcol + 7][lrow] = a1.w;
        Bs[lcol + 0][lrow] = b0.x; Bs[lcol + 1][lrow] = b0.y;
        Bs[lcol + 2][lrow] = b0.z; Bs[lcol + 3][lrow] = b0.w;
        Bs[lcol + 4][lrow] = b1.x; Bs[lcol + 5][lrow] = b1.y;
        Bs[lcol + 6][lrow] = b1.z; Bs[lcol + 7][lrow] = b1.w;
        __syncthreads();

#pragma unroll
        for (int kk = 0; kk < 16; kk++) {
            float4 aA = *(const float4*)&As[kk][tr * 4];
            float4 aB = *(const float4*)&As[kk][64 + tr * 4];
            float4 bA = *(const float4*)&Bs[kk][tc * 4];
            float4 bB = *(const float4*)&Bs[kk][64 + tc * 4];
            float av[8] = {aA.x, aA.y, aA.z, aA.w, aB.x, aB.y, aB.z, aB.w};
            float bv[8] = {bA.x, bA.y, bA.z, bA.w, bB.x, bB.y, bB.z, bB.w};
#pragma unroll
            for (int i = 0; i < 8; i++)
#pragma unroll
                for (int j = 0; j < 8; j++) acc[i][j] += av[i] * bv[j];
        }
        __syncthreads();
    }

#pragma unroll
    for (int i = 0; i < 8; i++) {
        const int m = m0 + ((i < 4) ? (tr * 4 + i) : (64 + tr * 4 + i - 4));
#pragma unroll
        for (int j = 0; j < 8; j++) {
            const int jj = n0 + ((j < 4) ? (tc * 4 + j) : (64 + tc * 4 + j - 4));
            out[(long)m * CDIM + jj] = acc[i][j] + pb[jj];
        }
    }
}

// ---------------------------------------------------------------------------
extern "C" void kernel_launch(void* const* d_in, const int* in_sizes, int n_in,
                              void* d_out, int out_size)
{
    const float* x    = (const float*)d_in[0];
    const float* qkvw = (const float*)d_in[1];
    const float* qb   = (const float*)d_in[2];
    const float* vb   = (const float*)d_in[3];
    const float* tbl  = (const float*)d_in[4];
    const float* pw   = (const float*)d_in[5];
    const float* pb   = (const float*)d_in[6];
    float* out = (float*)d_out;

    dim3 g1(QKVN / 128, M1 / 128);   // (18, 392)
    k_qkv<<<g1, 256>>>(x, qkvw, qb, vb);

    dim3 g2(NWIN, NHD);              // (256, 12)
    k_attn<<<g2, 224>>>(tbl);

    dim3 g3(CDIM / 128, M1 / 128);   // (6, 392)
    k_proj<<<g3, 256>>>(pw, pb, out);
}

// round 5
// speedup vs baseline: 1.7273x; 1.7273x over previous
#include <cuda_runtime.h>
#include <cuda_bf16.h>
#include <cstdint>

// Problem constants.
constexpr int CDIM = 768;
constexpr int NHD  = 12;
constexpr int HD   = 64;
constexpr int WSZ  = 14;
constexpr int NT   = WSZ * WSZ;        // 196
constexpr int NWIN = 256;
constexpr int M1   = NWIN * NT;        // 50176
constexpr int QKVN = 3 * CDIM;         // 2304

// GEMM tiling: CTA 128x128, K-chunk 32 fp32, 8 warps (4Mx2N), warp 32x64.
constexpr int KCH = 32;
constexpr int NCH = CDIM / KCH;        // 24

// smem byte offsets
constexpr int OFF_SA  = 0;             // fp32 A staging, 2 bufs x 16KB
constexpr int OFF_SB  = 32768;         // fp32 B staging, 2 bufs x 16KB
constexpr int OFF_AHI = 65536;         // bf16 tiles, 8KB each
constexpr int OFF_ALO = 73728;
constexpr int OFF_BHI = 81920;
constexpr int OFF_BLO = 90112;
constexpr int SMEM_TOT = 98304;        // 96 KB

// Scratch (device globals; runtime allocation is forbidden).
__device__ float g_q[(long)NWIN * NHD * NT * HD];
__device__ float g_k[(long)NWIN * NHD * NT * HD];
__device__ float g_v[(long)NWIN * NHD * NT * HD];
__device__ float g_att[(long)M1 * CDIM];

// ---------------------------------------------------------------------------
// PTX helpers (base-target instructions only: sm_80-era, safe on compute_103)
// ---------------------------------------------------------------------------
__device__ __forceinline__ uint32_t smem_u32(const void* p) {
    uint32_t a;
    asm("{ .reg .u64 t; cvta.to.shared.u64 t, %1; cvt.u32.u64 %0, t; }"
        : "=r"(a) : "l"(p));
    return a;
}
__device__ __forceinline__ void cp16(uint32_t dst, const void* src) {
    asm volatile("cp.async.cg.shared.global [%0], [%1], 16;"
                 :: "r"(dst), "l"(src));
}
__device__ __forceinline__ void cp_commit() {
    asm volatile("cp.async.commit_group;");
}
__device__ __forceinline__ void cp_wait1() {
    asm volatile("cp.async.wait_group 1;" ::: "memory");
}
__device__ __forceinline__ void cp_wait0() {
    asm volatile("cp.async.wait_group 0;" ::: "memory");
}
__device__ __forceinline__ void ldsm4(uint32_t* r, uint32_t addr) {
    asm volatile("ldmatrix.sync.aligned.m8n8.x4.shared.b16 {%0,%1,%2,%3}, [%4];"
                 : "=r"(r[0]), "=r"(r[1]), "=r"(r[2]), "=r"(r[3]) : "r"(addr));
}
__device__ __forceinline__ void mma16816(float* d, const uint32_t* a,
                                         uint32_t b0, uint32_t b1) {
    asm volatile(
        "mma.sync.aligned.m16n8k16.row.col.f32.bf16.bf16.f32 "
        "{%0,%1,%2,%3}, {%4,%5,%6,%7}, {%8,%9}, {%0,%1,%2,%3};"
        : "+f"(d[0]), "+f"(d[1]), "+f"(d[2]), "+f"(d[3])
        : "r"(a[0]), "r"(a[1]), "r"(a[2]), "r"(a[3]), "r"(b0), "r"(b1));
}

// 8 floats -> bf16 hi chunk (16B) + bf16 lo chunk (16B).
__device__ __forceinline__ void split8(float4 x, float4 y, uint4& hi, uint4& lo) {
    __nv_bfloat162 h0 = __floats2bfloat162_rn(x.x, x.y);
    __nv_bfloat162 h1 = __floats2bfloat162_rn(x.z, x.w);
    __nv_bfloat162 h2 = __floats2bfloat162_rn(y.x, y.y);
    __nv_bfloat162 h3 = __floats2bfloat162_rn(y.z, y.w);
    float2 g0 = __bfloat1622float2(h0), g1 = __bfloat1622float2(h1);
    float2 g2 = __bfloat1622float2(h2), g3 = __bfloat1622float2(h3);
    __nv_bfloat162 l0 = __floats2bfloat162_rn(x.x - g0.x, x.y - g0.y);
    __nv_bfloat162 l1 = __floats2bfloat162_rn(x.z - g1.x, x.w - g1.y);
    __nv_bfloat162 l2 = __floats2bfloat162_rn(y.x - g2.x, y.y - g2.y);
    __nv_bfloat162 l3 = __floats2bfloat162_rn(y.z - g3.x, y.w - g3.y);
    hi.x = *(uint32_t*)&h0; hi.y = *(uint32_t*)&h1;
    hi.z = *(uint32_t*)&h2; hi.w = *(uint32_t*)&h3;
    lo.x = *(uint32_t*)&l0; lo.y = *(uint32_t*)&l1;
    lo.z = *(uint32_t*)&l2; lo.w = *(uint32_t*)&l3;
}

// ---------------------------------------------------------------------------
// Shared GEMM mainloop. aRow/bRow: per-thread global row pointers (this
// thread's staging row, at column 0). acc: [2 mf][8 nf][4] fp32 accumulators.
// ---------------------------------------------------------------------------
__device__ __forceinline__ void gemm_main(char* sm, uint32_t smb,
                                          const float* aRow, const float* bRow,
                                          float acc[2][8][4]) {
    const int tid = threadIdx.x;
    const int lane = tid & 31, wid = tid >> 5;
    const int srow = tid >> 1, shalf = tid & 1;
    const int sswz = srow & 7;

    // -- stage issue (cp.async fp32 -> staging buf) --
    auto issue = [&](int c, int buf) {
        const float* as = aRow + c * KCH + shalf * 16;
        const float* bs = bRow + c * KCH + shalf * 16;
        const uint32_t da = smb + OFF_SA + buf * 16384 + srow * 128;
        const uint32_t db = smb + OFF_SB + buf * 16384 + srow * 128;
#pragma unroll
        for (int j = 0; j < 4; j++) {
            const int seg = shalf * 4 + j;
            const uint32_t po = (uint32_t)((seg ^ sswz) * 16);
            cp16(da + po, as + j * 4);
            cp16(db + po, bs + j * 4);
        }
        cp_commit();
    };

    // -- convert staging buf -> swizzled bf16 hi/lo tiles --
    auto convert = [&](int buf) {
        float4 fa[4], fb[4];
#pragma unroll
        for (int j = 0; j < 4; j++) {
            const int seg = shalf * 4 + j;
            const int po = (seg ^ sswz) * 16;
            fa[j] = *(const float4*)(sm + OFF_SA + buf * 16384 + srow * 128 + po);
            fb[j] = *(const float4*)(sm + OFF_SB + buf * 16384 + srow * 128 + po);
        }
        const int bswz = (srow >> 1) & 3;
#pragma unroll
        for (int h = 0; h < 2; h++) {          // two 8-float groups -> 2 chunks
            const int chunk = shalf * 2 + h;
            const int po = ((chunk ^ bswz) * 16);
            uint4 hi, lo;
            split8(fa[h * 2], fa[h * 2 + 1], hi, lo);
            *(uint4*)(sm + OFF_AHI + srow * 64 + po) = hi;
            *(uint4*)(sm + OFF_ALO + srow * 64 + po) = lo;
            split8(fb[h * 2], fb[h * 2 + 1], hi, lo);
            *(uint4*)(sm + OFF_BHI + srow * 64 + po) = hi;
            *(uint4*)(sm + OFF_BLO + srow * 64 + po) = lo;
        }
    };

    // -- per-warp compute geometry --
    const int m_base = (wid & 3) * 32;
    const int n_base = (wid >> 2) * 64;
    const int lr = lane & 15, lh = lane >> 4;
    const int rA = m_base + lr;
    const int rB = n_base + lr;
    const uint32_t swA = (rA >> 1) & 3;   // invariant across mf (+16 rows)
    const uint32_t swB = (rB >> 1) & 3;   // invariant across nfp (+16 rows)
    const uint32_t aHi = smb + OFF_AHI + rA * 64;
    const uint32_t aLo = smb + OFF_ALO + rA * 64;
    const uint32_t bHi = smb + OFF_BHI + rB * 64;
    const uint32_t bLo = smb + OFF_BLO + rB * 64;

    issue(0, 0);
    for (int c = 0; c < NCH; c++) {
        if (c + 1 < NCH) { issue(c + 1, (c + 1) & 1); cp_wait1(); }
        else             { cp_wait0(); }
        __syncthreads();                 // staging ready, prev compute done
        convert(c & 1);
        __syncthreads();                 // bf16 tiles ready

#pragma unroll
        for (int s = 0; s < 2; s++) {
            const uint32_t ch = 2 * s + lh;
            const uint32_t pa = (ch ^ swA) * 16;
            const uint32_t pb = (ch ^ swB) * 16;
            uint32_t ah[2][4], al[2][4];
            ldsm4(ah[0], aHi + pa); ldsm4(ah[1], aHi + 1024 + pa);
            ldsm4(al[0], aLo + pa); ldsm4(al[1], aLo + 1024 + pa);
#pragma unroll
            for (int nfp = 0; nfp < 4; nfp++) {
                uint32_t bh[4], bl[4];
                ldsm4(bh, bHi + nfp * 1024 + pb);
                ldsm4(bl, bLo + nfp * 1024 + pb);
#pragma unroll
                for (int mf = 0; mf < 2; mf++)
#pragma unroll
                    for (int q = 0; q < 2; q++) {
                        float* d = acc[mf][nfp * 2 + q];
                        mma16816(d, ah[mf], bh[q], bh[q + 2]);   // hi*hi
                        mma16816(d, ah[mf], bl[q], bl[q + 2]);   // hi*lo
                        mma16816(d, al[mf], bh[q], bh[q + 2]);   // lo*hi
                    }
            }
        }
    }
}

// ---------------------------------------------------------------------------
// Kernel 1: fused window-partition + QKV GEMM (mma.sync bf16 hi/lo split)
// ---------------------------------------------------------------------------
__global__ __launch_bounds__(256, 2) void k_qkv_mma(
    const float* __restrict__ x, const float* __restrict__ w,
    const float* __restrict__ qb, const float* __restrict__ vb)
{
    extern __shared__ char sm[];
    const uint32_t smb = smem_u32(sm);
    const int tid = threadIdx.x;
    const int lane = tid & 31, wid = tid >> 5;
    const int bn = blockIdx.x, bm = blockIdx.y;
    const int m0 = bm * 128, n0 = bn * 128;

    // A row pointer through the window permutation.
    const float* aRow;
    {
        const int srow = tid >> 1;
        const int am = m0 + srow;
        const int wwin = am / NT;
        const int nn = am - wwin * NT;
        const int bimg = wwin >> 4, wi = wwin & 15;
        const int rr = (wi >> 2) * WSZ + nn / WSZ;
        const int cc = (wi & 3) * WSZ + nn % WSZ;
        aRow = x + ((long)bimg * 3136 + (long)rr * 56 + cc) * CDIM;
    }
    const float* bRow = w + (long)(n0 + (tid >> 1)) * CDIM;

    float acc[2][8][4];
#pragma unroll
    for (int a = 0; a < 2; a++)
#pragma unroll
        for (int b = 0; b < 8; b++)
#pragma unroll
            for (int c = 0; c < 4; c++) acc[a][b][c] = 0.f;

    gemm_main(sm, smb, aRow, bRow, acc);

    // Epilogue: scatter into q/k/v, [win, head, tok, hd] layout.
    const int m_base = (wid & 3) * 32, n_base = (wid >> 2) * 64;
    const int qrow = lane >> 2, qcol = (lane & 3) * 2;
    const int part = n0 / CDIM;              // 0:q 1:k 2:v
    const int jrbase = n0 - part * CDIM + n_base;  // multiple of 64
    const int hh = jrbase >> 6;
    float* dst = (part == 0) ? g_q : (part == 1) ? g_k : g_v;

#pragma unroll
    for (int mf = 0; mf < 2; mf++)
#pragma unroll
        for (int half = 0; half < 2; half++) {
            const int rl = m_base + mf * 16 + half * 8 + qrow;
            const int m = m0 + rl;
            const int w2 = m / NT, n2 = m - w2 * NT;
            float* rp = dst + (long)w2 * (NHD * NT * HD)
                            + ((long)hh * NT + n2) * HD;
#pragma unroll
            for (int nf = 0; nf < 8; nf++) {
                const int dd = nf * 8 + qcol;
                float vx = acc[mf][nf][half * 2 + 0];
                float vy = acc[mf][nf][half * 2 + 1];
                const int jr = jrbase + dd;
                if (part == 0) {
                    vx = (vx + qb[jr]) * 0.125f;
                    vy = (vy + qb[jr + 1]) * 0.125f;
                } else if (part == 2) {
                    vx += vb[jr]; vy += vb[jr + 1];
                }
                *(float2*)(rp + dd) = make_float2(vx, vy);
            }
        }
}

// ---------------------------------------------------------------------------
// Kernel 2: windowed attention (fp32 flash-style; unchanged this round)
// ---------------------------------------------------------------------------
__global__ __launch_bounds__(224) void k_attn(const float* __restrict__ table)
{
    const int w  = blockIdx.x;
    const int h  = blockIdx.y;
    const int tid = threadIdx.x;

    __shared__ float Ks[14][64];
    __shared__ float Vs[14][64];
    __shared__ float tb[729];

    for (int t = tid; t < 729; t += 224) tb[t] = table[t * NHD + h];

    const long base = ((long)w * NHD + h) * NT * HD;
    const int i  = tid;
    const int iy = i / WSZ;
    const int ix = i - iy * WSZ;

    float4 q4[16];
    float4 o4[16];
    float mmax = -1e30f, lsum = 0.f;
    if (i < NT) {
        const float4* qp = (const float4*)(g_q + base + (long)i * HD);
#pragma unroll
        for (int kk = 0; kk < 16; kk++) {
            q4[kk] = qp[kk];
            o4[kk] = make_float4(0.f, 0.f, 0.f, 0.f);
        }
    }
    __syncthreads();

    for (int jt = 0; jt < 14; jt++) {
        const float4* kp = (const float4*)(g_k + base + (long)jt * 14 * HD);
        const float4* vp = (const float4*)(g_v + base + (long)jt * 14 * HD);
        ((float4*)Ks)[tid] = kp[tid];
        ((float4*)Vs)[tid] = vp[tid];
        __syncthreads();

        if (i < NT) {
            float s[14];
            float tmax = -1e30f;
#pragma unroll
            for (int jj = 0; jj < 14; jj++) {
                const float4* kr = (const float4*)Ks[jj];
                float a0 = 0.f, a1 = 0.f, a2 = 0.f, a3 = 0.f;
#pragma unroll
                for (int kk = 0; kk < 16; kk++) {
                    float4 kv = kr[kk];
                    float4 qv = q4[kk];
                    a0 += qv.x * kv.x; a1 += qv.y * kv.y;
                    a2 += qv.z * kv.z; a3 += qv.w * kv.w;
                }
                float sc = (a0 + a1) + (a2 + a3);
                sc += tb[(iy - jt + 13) * 27 + (ix - jj + 13)];
                s[jj] = sc;
                tmax = fmaxf(tmax, sc);
            }
            const float mnew = fmaxf(mmax, tmax);
            const float corr = __expf(mmax - mnew);
            mmax = mnew;
            lsum *= corr;
#pragma unroll
            for (int kk = 0; kk < 16; kk++) {
                o4[kk].x *= corr; o4[kk].y *= corr;
                o4[kk].z *= corr; o4[kk].w *= corr;
            }
#pragma unroll
            for (int jj = 0; jj < 14; jj++) {
                const float p = __expf(s[jj] - mmax);
                lsum += p;
                const float4* vr = (const float4*)Vs[jj];
#pragma unroll
                for (int kk = 0; kk < 16; kk++) {
                    float4 vv = vr[kk];
                    o4[kk].x += p * vv.x; o4[kk].y += p * vv.y;
                    o4[kk].z += p * vv.z; o4[kk].w += p * vv.w;
                }
            }
        }
        __syncthreads();
    }

    if (i < NT) {
        const float inv = 1.f / lsum;
        const int bimg = w >> 4, wi = w & 15;
        const int r = (wi >> 2) * WSZ + iy;
        const int c = (wi & 3) * WSZ + ix;
        float4* op = (float4*)(g_att + ((long)bimg * 3136 + (long)r * 56 + c) * CDIM + h * HD);
#pragma unroll
        for (int kk = 0; kk < 16; kk++) {
            float4 t = o4[kk];
            op[kk] = make_float4(t.x * inv, t.y * inv, t.z * inv, t.w * inv);
        }
    }
}

// ---------------------------------------------------------------------------
// Kernel 3: output projection GEMM (mma.sync bf16 hi/lo split)
// ---------------------------------------------------------------------------
__global__ __launch_bounds__(256, 2) void k_proj_mma(
    const float* __restrict__ pw, const float* __restrict__ pb,
    float* __restrict__ out)
{
    extern __shared__ char sm[];
    const uint32_t smb = smem_u32(sm);
    const int tid = threadIdx.x;
    const int lane = tid & 31, wid = tid >> 5;
    const int bn = blockIdx.x, bm = blockIdx.y;
    const int m0 = bm * 128, n0 = bn * 128;

    const float* aRow = g_att + (long)(m0 + (tid >> 1)) * CDIM;
    const float* bRow = pw + (long)(n0 + (tid >> 1)) * CDIM;

    float acc[2][8][4];
#pragma unroll
    for (int a = 0; a < 2; a++)
#pragma unroll
        for (int b = 0; b < 8; b++)
#pragma unroll
            for (int c = 0; c < 4; c++) acc[a][b][c] = 0.f;

    gemm_main(sm, smb, aRow, bRow, acc);

    const int m_base = (wid & 3) * 32, n_base = (wid >> 2) * 64;
    const int qrow = lane >> 2, qcol = (lane & 3) * 2;

#pragma unroll
    for (int mf = 0; mf < 2; mf++)
#pragma unroll
        for (int half = 0; half < 2; half++) {
            const int rl = m_base + mf * 16 + half * 8 + qrow;
            const int m = m0 + rl;
            float* rp = out + (long)m * CDIM + n0 + n_base;
#pragma unroll
            for (int nf = 0; nf < 8; nf++) {
                const int dd = nf * 8 + qcol;
                const float2 bias = *(const float2*)(pb + n0 + n_base + dd);
                *(float2*)(rp + dd) = make_float2(
                    acc[mf][nf][half * 2 + 0] + bias.x,
                    acc[mf][nf][half * 2 + 1] + bias.y);
            }
        }
}

// ---------------------------------------------------------------------------
extern "C" void kernel_launch(void* const* d_in, const int* in_sizes, int n_in,
                              void* d_out, int out_size)
{
    const float* x    = (const float*)d_in[0];
    const float* qkvw = (const float*)d_in[1];
    const float* qb   = (const float*)d_in[2];
    const float* vb   = (const float*)d_in[3];
    const float* tbl  = (const float*)d_in[4];
    const float* pw   = (const float*)d_in[5];
    const float* pb   = (const float*)d_in[6];
    float* out = (float*)d_out;

    static bool attr_done = false;
    if (!attr_done) {
        cudaFuncSetAttribute(k_qkv_mma,
                             cudaFuncAttributeMaxDynamicSharedMemorySize, SMEM_TOT);
        cudaFuncSetAttribute(k_proj_mma,
                             cudaFuncAttributeMaxDynamicSharedMemorySize, SMEM_TOT);
        attr_done = true;
    }

    dim3 g1(QKVN / 128, M1 / 128);   // (18, 392)
    k_qkv_mma<<<g1, 256, SMEM_TOT>>>(x, qkvw, qb, vb);

    dim3 g2(NWIN, NHD);              // (256, 12)
    k_attn<<<g2, 224>>>(tbl);

    dim3 g3(CDIM / 128, M1 / 128);   // (6, 392)
    k_proj_mma<<<g3, 256, SMEM_TOT>>>(pw, pb, out);
}

// round 7
// speedup vs baseline: 1.7420x; 1.0085x over previous
#include <cuda_runtime.h>
#include <cuda_bf16.h>
#include <cstdint>

// Problem constants.
constexpr int CDIM = 768;
constexpr int NHD  = 12;
constexpr int HD   = 64;
constexpr int WSZ  = 14;
constexpr int NT   = WSZ * WSZ;        // 196
constexpr int NWIN = 256;
constexpr int M1   = NWIN * NT;        // 50176
constexpr int QKVN = 3 * CDIM;         // 2304

// GEMM tiling: CTA 128x128, K-chunk 32 (bf16), 8 warps (4Mx2N), warp 32x64.
constexpr int KCH = 32;
constexpr int NCH = CDIM / KCH;        // 24
constexpr int NSTG = 3;
// Per-stage smem layout (bytes): Ahi, Alo, Bhi, Blo tiles of 128 rows x 64B.
constexpr int T_AHI = 0;
constexpr int T_ALO = 8192;
constexpr int T_BHI = 16384;
constexpr int T_BLO = 24576;
constexpr int STG_B = 32768;
constexpr int SMEM_TOT = NSTG * STG_B;  // 96 KB

// Scratch (device globals; runtime allocation is forbidden).
__device__ float g_q[(long)NWIN * NHD * NT * HD];
__device__ float g_k[(long)NWIN * NHD * NT * HD];
__device__ float g_v[(long)NWIN * NHD * NT * HD];
__device__ __nv_bfloat16 g_xhi[(long)M1 * CDIM];
__device__ __nv_bfloat16 g_xlo[(long)M1 * CDIM];
__device__ __nv_bfloat16 g_whi[(long)QKVN * CDIM];
__device__ __nv_bfloat16 g_wlo[(long)QKVN * CDIM];
__device__ __nv_bfloat16 g_pwhi[(long)CDIM * CDIM];
__device__ __nv_bfloat16 g_pwlo[(long)CDIM * CDIM];
__device__ __nv_bfloat16 g_ahi[(long)M1 * CDIM];
__device__ __nv_bfloat16 g_alo[(long)M1 * CDIM];

// ---------------------------------------------------------------------------
// PTX helpers (base-target instructions only; tcgen05 is rejected by ptxas
// on the harness's compute_103 virtual target).
// ---------------------------------------------------------------------------
__device__ __forceinline__ uint32_t smem_u32(const void* p) {
    uint32_t a;
    asm("{ .reg .u64 t; cvta.to.shared.u64 t, %1; cvt.u32.u64 %0, t; }"
        : "=r"(a) : "l"(p));
    return a;
}
__device__ __forceinline__ void cp16(uint32_t dst, const void* src) {
    asm volatile("cp.async.cg.shared.global [%0], [%1], 16;"
                 :: "r"(dst), "l"(src));
}
__device__ __forceinline__ void cp_commit() {
    asm volatile("cp.async.commit_group;");
}
__device__ __forceinline__ void cp_wait1() {
    asm volatile("cp.async.wait_group 1;" ::: "memory");
}
__device__ __forceinline__ void cp_wait0() {
    asm volatile("cp.async.wait_group 0;" ::: "memory");
}
__device__ __forceinline__ void ldsm4(uint32_t* r, uint32_t addr) {
    asm volatile("ldmatrix.sync.aligned.m8n8.x4.shared.b16 {%0,%1,%2,%3}, [%4];"
                 : "=r"(r[0]), "=r"(r[1]), "=r"(r[2]), "=r"(r[3]) : "r"(addr));
}
__device__ __forceinline__ void mma16816(float* d, const uint32_t* a,
                                         uint32_t b0, uint32_t b1) {
    asm volatile(
        "mma.sync.aligned.m16n8k16.row.col.f32.bf16.bf16.f32 "
        "{%0,%1,%2,%3}, {%4,%5,%6,%7}, {%8,%9}, {%0,%1,%2,%3};"
        : "+f"(d[0]), "+f"(d[1]), "+f"(d[2]), "+f"(d[3])
        : "r"(a[0]), "r"(a[1]), "r"(a[2]), "r"(a[3]), "r"(b0), "r"(b1));
}

// 4 floats -> bf16 hi (8B) + bf16 lo (8B).
__device__ __forceinline__ void split4(float4 v, uint2& hi, uint2& lo) {
    __nv_bfloat162 h0 = __floats2bfloat162_rn(v.x, v.y);
    __nv_bfloat162 h1 = __floats2bfloat162_rn(v.z, v.w);
    float2 f0 = __bfloat1622float2(h0);
    float2 f1 = __bfloat1622float2(h1);
    __nv_bfloat162 l0 = __floats2bfloat162_rn(v.x - f0.x, v.y - f0.y);
    __nv_bfloat162 l1 = __floats2bfloat162_rn(v.z - f1.x, v.w - f1.y);
    hi.x = *(uint32_t*)&h0; hi.y = *(uint32_t*)&h1;
    lo.x = *(uint32_t*)&l0; lo.y = *(uint32_t*)&l1;
}

// ---------------------------------------------------------------------------
// Kernel 0: fp32 -> bf16 hi/lo conversion (elementwise, grid-stride-free).
// ---------------------------------------------------------------------------
__global__ __launch_bounds__(256) void k_cvt(const float* __restrict__ src,
                                            __nv_bfloat16* __restrict__ hi,
                                            __nv_bfloat16* __restrict__ lo,
                                            long n4)
{
    const long i = (long)blockIdx.x * blockDim.x + threadIdx.x;
    if (i >= n4) return;
    float4 v = *(const float4*)(src + i * 4);
    uint2 h, l;
    split4(v, h, l);
    *(uint2*)(hi + i * 4) = h;
    *(uint2*)(lo + i * 4) = l;
}

// ---------------------------------------------------------------------------
// Shared bf16 GEMM mainloop (3-term split accumulate).
// aHiR/aLoR/bHiR/bLoR: per-thread global row pointers (this thread's load row,
// at column 0, element stride CDIM). acc: [2 mf][8 nf][4].
// ---------------------------------------------------------------------------
__device__ __forceinline__ void gemm_main(uint32_t smb,
                                          const __nv_bfloat16* aHiR,
                                          const __nv_bfloat16* aLoR,
                                          const __nv_bfloat16* bHiR,
                                          const __nv_bfloat16* bLoR,
                                          float acc[2][8][4]) {
    const int tid = threadIdx.x;
    const int lane = tid & 31, wid = tid >> 5;
    const int srow = tid >> 1, shalf = tid & 1;
    const int bswz = (srow >> 1) & 3;

    // Destination offsets for this thread's two 16B chunks (within a stage).
    const uint32_t d0 = srow * 64 + (((shalf * 2 + 0) ^ bswz) * 16);
    const uint32_t d1 = srow * 64 + (((shalf * 2 + 1) ^ bswz) * 16);
    const int e0 = (shalf * 2 + 0) * 8;   // element offset of chunk 0
    const int e1 = (shalf * 2 + 1) * 8;

    auto issue = [&](int c, int stg) {
        const uint32_t st = smb + stg * STG_B;
        const int kb = c * KCH;
        cp16(st + T_AHI + d0, aHiR + kb + e0);
        cp16(st + T_AHI + d1, aHiR + kb + e1);
        cp16(st + T_ALO + d0, aLoR + kb + e0);
        cp16(st + T_ALO + d1, aLoR + kb + e1);
        cp16(st + T_BHI + d0, bHiR + kb + e0);
        cp16(st + T_BHI + d1, bHiR + kb + e1);
        cp16(st + T_BLO + d0, bLoR + kb + e0);
        cp16(st + T_BLO + d1, bLoR + kb + e1);
        cp_commit();
    };

    // Per-warp compute geometry (hoisted).
    const int m_base = (wid & 3) * 32;
    const int n_base = (wid >> 2) * 64;
    const int lr = lane & 15, lh = lane >> 4;
    const int rA = m_base + lr;
    const int rB = n_base + lr;
    const uint32_t swA = (rA >> 1) & 3;   // invariant under +16 rows
    const uint32_t swB = (rB >> 1) & 3;
    // ldsm chunk offsets for the two k-steps.
    const uint32_t paS[2] = {((0 + lh) ^ swA) * 16, ((2 + lh) ^ swA) * 16};
    const uint32_t pbS[2] = {((0 + lh) ^ swB) * 16, ((2 + lh) ^ swB) * 16};
    const uint32_t rA64 = rA * 64, rB64 = rB * 64;

    issue(0, 0);
    issue(1, 1);
    for (int c = 0; c < NCH; c++) {
        const int stg = c % NSTG;
        if (c + 1 < NCH) cp_wait1(); else cp_wait0();
        __syncthreads();
        if (c + 2 < NCH) issue(c + 2, (c + 2) % NSTG);

        const uint32_t st = smb + stg * STG_B;
        const uint32_t aHi = st + T_AHI + rA64;
        const uint32_t aLo = st + T_ALO + rA64;
        const uint32_t bHi = st + T_BHI + rB64;
        const uint32_t bLo = st + T_BLO + rB64;

#pragma unroll
        for (int s = 0; s < 2; s++) {
            const uint32_t pa = paS[s], pb = pbS[s];
            uint32_t ah[2][4], al[2][4];
            ldsm4(ah[0], aHi + pa); ldsm4(ah[1], aHi + 1024 + pa);
            ldsm4(al[0], aLo + pa); ldsm4(al[1], aLo + 1024 + pa);
#pragma unroll
            for (int nfp = 0; nfp < 4; nfp++) {
                uint32_t bh[4], bl[4];
                ldsm4(bh, bHi + nfp * 1024 + pb);
                ldsm4(bl, bLo + nfp * 1024 + pb);
#pragma unroll
                for (int mf = 0; mf < 2; mf++)
#pragma unroll
                    for (int q = 0; q < 2; q++) {
                        float* d = acc[mf][nfp * 2 + q];
                        mma16816(d, ah[mf], bh[q], bh[q + 2]);   // hi*hi
                        mma16816(d, ah[mf], bl[q], bl[q + 2]);   // hi*lo
                        mma16816(d, al[mf], bh[q], bh[q + 2]);   // lo*hi
                    }
            }
        }
    }
}

// ---------------------------------------------------------------------------
// Kernel 1: fused window-partition + QKV GEMM (bf16 inputs from g_xhi/lo)
// ---------------------------------------------------------------------------
__global__ __launch_bounds__(256, 2) void k_qkv_mma(
    const float* __restrict__ qb, const float* __restrict__ vb)
{
    extern __shared__ char sm[];
    const uint32_t smb = smem_u32(sm);
    const int tid = threadIdx.x;
    const int lane = tid & 31, wid = tid >> 5;
    const int bn = blockIdx.x, bm = blockIdx.y;
    const int m0 = bm * 128, n0 = bn * 128;

    // A row through the window permutation (applied to the bf16 copies of x).
    long aoff;
    {
        const int srow = tid >> 1;
        const int am = m0 + srow;
        const int wwin = am / NT;
        const int nn = am - wwin * NT;
        const int bimg = wwin >> 4, wi = wwin & 15;
        const int rr = (wi >> 2) * WSZ + nn / WSZ;
        const int cc = (wi & 3) * WSZ + nn % WSZ;
        aoff = ((long)bimg * 3136 + (long)rr * 56 + cc) * CDIM;
    }
    const long boff = (long)(n0 + (tid >> 1)) * CDIM;

    float acc[2][8][4];
#pragma unroll
    for (int a = 0; a < 2; a++)
#pragma unroll
        for (int b = 0; b < 8; b++)
#pragma unroll
            for (int c = 0; c < 4; c++) acc[a][b][c] = 0.f;

    gemm_main(smb, g_xhi + aoff, g_xlo + aoff, g_whi + boff, g_wlo + boff, acc);

    // Epilogue: scatter into q/k/v, [win, head, tok, hd] layout (fp32).
    const int m_base = (wid & 3) * 32, n_base = (wid >> 2) * 64;
    const int qrow = lane >> 2, qcol = (lane & 3) * 2;
    const int part = n0 / CDIM;              // 0:q 1:k 2:v
    const int jrbase = n0 - part * CDIM + n_base;
    const int hh = jrbase >> 6;
    float* dst = (part == 0) ? g_q : (part == 1) ? g_k : g_v;

#pragma unroll
    for (int mf = 0; mf < 2; mf++)
#pragma unroll
        for (int half = 0; half < 2; half++) {
            const int rl = m_base + mf * 16 + half * 8 + qrow;
            const int m = m0 + rl;
            const int w2 = m / NT, n2 = m - w2 * NT;
            float* rp = dst + (long)w2 * (NHD * NT * HD)
                            + ((long)hh * NT + n2) * HD;
#pragma unroll
            for (int nf = 0; nf < 8; nf++) {
                const int dd = nf * 8 + qcol;
                float vx = acc[mf][nf][half * 2 + 0];
                float vy = acc[mf][nf][half * 2 + 1];
                const int jr = jrbase + dd;
                if (part == 0) {
                    vx = (vx + qb[jr]) * 0.125f;
                    vy = (vy + qb[jr + 1]) * 0.125f;
                } else if (part == 2) {
                    vx += vb[jr]; vy += vb[jr + 1];
                }
                *(float2*)(rp + dd) = make_float2(vx, vy);
            }
        }
}

// ---------------------------------------------------------------------------
// Kernel 2: windowed attention (fp32 flash-style); epilogue emits bf16 hi/lo
// pairs directly for the projection GEMM.
// ---------------------------------------------------------------------------
__global__ __launch_bounds__(224) void k_attn(const float* __restrict__ table)
{
    const int w  = blockIdx.x;
    const int h  = blockIdx.y;
    const int tid = threadIdx.x;

    __shared__ float Ks[14][64];
    __shared__ float Vs[14][64];
    __shared__ float tb[729];

    for (int t = tid; t < 729; t += 224) tb[t] = table[t * NHD + h];

    const long base = ((long)w * NHD + h) * NT * HD;
    const int i  = tid;
    const int iy = i / WSZ;
    const int ix = i - iy * WSZ;

    float4 q4[16];
    float4 o4[16];
    float mmax = -1e30f, lsum = 0.f;
    if (i < NT) {
        const float4* qp = (const float4*)(g_q + base + (long)i * HD);
#pragma unroll
        for (int kk = 0; kk < 16; kk++) {
            q4[kk] = qp[kk];
            o4[kk] = make_float4(0.f, 0.f, 0.f, 0.f);
        }
    }
    __syncthreads();

    for (int jt = 0; jt < 14; jt++) {
        const float4* kp = (const float4*)(g_k + base + (long)jt * 14 * HD);
        const float4* vp = (const float4*)(g_v + base + (long)jt * 14 * HD);
        ((float4*)Ks)[tid] = kp[tid];
        ((float4*)Vs)[tid] = vp[tid];
        __syncthreads();

        if (i < NT) {
            float s[14];
            float tmax = -1e30f;
#pragma unroll
            for (int jj = 0; jj < 14; jj++) {
                const float4* kr = (const float4*)Ks[jj];
                float a0 = 0.f, a1 = 0.f, a2 = 0.f, a3 = 0.f;
#pragma unroll
                for (int kk = 0; kk < 16; kk++) {
                    float4 kv = kr[kk];
                    float4 qv = q4[kk];
                    a0 += qv.x * kv.x; a1 += qv.y * kv.y;
                    a2 += qv.z * kv.z; a3 += qv.w * kv.w;
                }
                float sc = (a0 + a1) + (a2 + a3);
                sc += tb[(iy - jt + 13) * 27 + (ix - jj + 13)];
                s[jj] = sc;
                tmax = fmaxf(tmax, sc);
            }
            const float mnew = fmaxf(mmax, tmax);
            const float corr = __expf(mmax - mnew);
            mmax = mnew;
            lsum *= corr;
#pragma unroll
            for (int kk = 0; kk < 16; kk++) {
                o4[kk].x *= corr; o4[kk].y *= corr;
                o4[kk].z *= corr; o4[kk].w *= corr;
            }
#pragma unroll
            for (int jj = 0; jj < 14; jj++) {
                const float p = __expf(s[jj] - mmax);
                lsum += p;
                const float4* vr = (const float4*)Vs[jj];
#pragma unroll
                for (int kk = 0; kk < 16; kk++) {
                    float4 vv = vr[kk];
                    o4[kk].x += p * vv.x; o4[kk].y += p * vv.y;
                    o4[kk].z += p * vv.z; o4[kk].w += p * vv.w;
                }
            }
        }
        __syncthreads();
    }

    if (i < NT) {
        const float inv = 1.f / lsum;
        const int bimg = w >> 4, wi = w & 15;
        const int r = (wi >> 2) * WSZ + iy;
        const int c = (wi & 3) * WSZ + ix;
        const long ob = ((long)bimg * 3136 + (long)r * 56 + c) * CDIM + h * HD;
#pragma unroll
        for (int kk = 0; kk < 16; kk++) {
            float4 t = o4[kk];
            t.x *= inv; t.y *= inv; t.z *= inv; t.w *= inv;
            uint2 hi, lo;
            split4(t, hi, lo);
            *(uint2*)(g_ahi + ob + kk * 4) = hi;
            *(uint2*)(g_alo + ob + kk * 4) = lo;
        }
    }
}

// ---------------------------------------------------------------------------
// Kernel 3: output projection GEMM (bf16 inputs from g_ahi/lo, g_pwhi/lo)
// ---------------------------------------------------------------------------
__global__ __launch_bounds__(256, 2) void k_proj_mma(
    const float* __restrict__ pb, float* __restrict__ out)
{
    extern __shared__ char sm[];
    const uint32_t smb = smem_u32(sm);
    const int tid = threadIdx.x;
    const int lane = tid & 31, wid = tid >> 5;
    const int bn = blockIdx.x, bm = blockIdx.y;
    const int m0 = bm * 128, n0 = bn * 128;

    const long aoff = (long)(m0 + (tid >> 1)) * CDIM;
    const long boff = (long)(n0 + (tid >> 1)) * CDIM;

    float acc[2][8][4];
#pragma unroll
    for (int a = 0; a < 2; a++)
#pragma unroll
        for (int b = 0; b < 8; b++)
#pragma unroll
            for (int c = 0; c < 4; c++) acc[a][b][c] = 0.f;

    gemm_main(smb, g_ahi + aoff, g_alo + aoff, g_pwhi + boff, g_pwlo + boff, acc);

    const int m_base = (wid & 3) * 32, n_base = (wid >> 2) * 64;
    const int qrow = lane >> 2, qcol = (lane & 3) * 2;

#pragma unroll
    for (int mf = 0; mf < 2; mf++)
#pragma unroll
        for (int half = 0; half < 2; half++) {
            const int rl = m_base + mf * 16 + half * 8 + qrow;
            const int m = m0 + rl;
            float* rp = out + (long)m * CDIM + n0 + n_base;
#pragma unroll
            for (int nf = 0; nf < 8; nf++) {
                const int dd = nf * 8 + qcol;
                const float2 bias = *(const float2*)(pb + n0 + n_base + dd);
                *(float2*)(rp + dd) = make_float2(
                    acc[mf][nf][half * 2 + 0] + bias.x,
                    acc[mf][nf][half * 2 + 1] + bias.y);
            }
        }
}

// ---------------------------------------------------------------------------
extern "C" void kernel_launch(void* const* d_in, const int* in_sizes, int n_in,
                              void* d_out, int out_size)
{
    const float* x    = (const float*)d_in[0];
    const float* qkvw = (const float*)d_in[1];
    const float* qb   = (const float*)d_in[2];
    const float* vb   = (const float*)d_in[3];
    const float* tbl  = (const float*)d_in[4];
    const float* pw   = (const float*)d_in[5];
    const float* pb   = (const float*)d_in[6];
    float* out = (float*)d_out;

    static bool attr_done = false;
    if (!attr_done) {
        cudaFuncSetAttribute(k_qkv_mma,
                             cudaFuncAttributeMaxDynamicSharedMemorySize, SMEM_TOT);
        cudaFuncSetAttribute(k_proj_mma,
                             cudaFuncAttributeMaxDynamicSharedMemorySize, SMEM_TOT);
        attr_done = true;
    }

    __nv_bfloat16 *xhi, *xlo, *whi, *wlo, *pwhi, *pwlo;
    cudaGetSymbolAddress((void**)&xhi, g_xhi);
    cudaGetSymbolAddress((void**)&xlo, g_xlo);
    cudaGetSymbolAddress((void**)&whi, g_whi);
    cudaGetSymbolAddress((void**)&wlo, g_wlo);
    cudaGetSymbolAddress((void**)&pwhi, g_pwhi);
    cudaGetSymbolAddress((void**)&pwlo, g_pwlo);

    // Pre-convert fp32 operands to bf16 hi/lo.
    {
        const long n4x = (long)M1 * CDIM / 4;
        k_cvt<<<(unsigned)((n4x + 255) / 256), 256>>>(x, xhi, xlo, n4x);
        const long n4w = (long)QKVN * CDIM / 4;
        k_cvt<<<(unsigned)((n4w + 255) / 256), 256>>>(qkvw, whi, wlo, n4w);
        const long n4p = (long)CDIM * CDIM / 4;
        k_cvt<<<(unsigned)((n4p + 255) / 256), 256>>>(pw, pwhi, pwlo, n4p);
    }

    dim3 g1(QKVN / 128, M1 / 128);   // (18, 392)
    k_qkv_mma<<<g1, 256, SMEM_TOT>>>(qb, vb);

    dim3 g2(NWIN, NHD);              // (256, 12)
    k_attn<<<g2, 224>>>(tbl);

    dim3 g3(CDIM / 128, M1 / 128);   // (6, 392)
    k_proj_mma<<<g3, 256, SMEM_TOT>>>(pb, out);
}